// round 9
// baseline (speedup 1.0000x reference)
#include <cuda_runtime.h>
#include <cuda_bf16.h>

// x (64, 96, 8, 8) fp32 -> out (64, 96, 96, 8, 8, 2) fp32
// out[b,i,j,c1,c2,0] = x[b,i,c1,c2]; out[b,i,j,c1,c2,1] = x[b,j,c1,c2]
//
// Block = (b, i-pair, j-tile of 32). Warp w covers j = jt*32 + w*4 + {0..3},
// lane = k2 (float2 index within the 64-float block).
// Per thread: 2 xi loads + 4 xj loads -> 8 independent 512B-coalesced stores.
// xj values are reused across both i's (halves xj load traffic vs R6).

#define GS  96
#define BLK 64            // 8*8 floats per group block
#define F4  32            // float4 per (b,i,j) pair
#define JT  3             // j-tiles per i-pair: 3 * 32 = 96
#define IH  48            // i-pairs per b: 96 / 2

__global__ __launch_bounds__(256)
void gcom_kernel(const float* __restrict__ x, float4* __restrict__ out)
{
    unsigned blk = blockIdx.x;             // ((b*48 + ih)*3 + jt)
    unsigned jt  = blk % JT;
    unsigned u   = blk / JT;               // b*48 + ih
    unsigned b   = u / IH;
    unsigned ih  = u - b * IH;
    unsigned i0  = ih * 2;                 // first of 2 i's

    unsigned lane = threadIdx.x & 31u;     // k2
    unsigned w    = threadIdx.x >> 5;      // warp 0..7
    unsigned j0   = jt * 32 + w * 4;       // first of 4 j's for this warp

    const float2* xrow = (const float2*)(x + (size_t)b * GS * BLK);

    // All loads issued up front.
    float2 a0 = __ldg(xrow + i0 * F4 + lane);
    float2 a1 = __ldg(xrow + (i0 + 1) * F4 + lane);
    const float2* xj = xrow + j0 * F4 + lane;
    float2 c0 = __ldg(xj);
    float2 c1 = __ldg(xj + F4);
    float2 c2 = __ldg(xj + 2 * F4);
    float2 c3 = __ldg(xj + 3 * F4);

    // 8 independent stores: 2 i's x 4 j's.
    float4* o0 = out + ((size_t)(b * GS + i0) * GS + j0) * F4 + lane;
    float4* o1 = o0 + (size_t)GS * F4;     // row i0+1

    o0[0]      = make_float4(a0.x, c0.x, a0.y, c0.y);
    o0[F4]     = make_float4(a0.x, c1.x, a0.y, c1.y);
    o0[2 * F4] = make_float4(a0.x, c2.x, a0.y, c2.y);
    o0[3 * F4] = make_float4(a0.x, c3.x, a0.y, c3.y);

    o1[0]      = make_float4(a1.x, c0.x, a1.y, c0.y);
    o1[F4]     = make_float4(a1.x, c1.x, a1.y, c1.y);
    o1[2 * F4] = make_float4(a1.x, c2.x, a1.y, c2.y);
    o1[3 * F4] = make_float4(a1.x, c3.x, a1.y, c3.y);
}

extern "C" void kernel_launch(void* const* d_in, const int* in_sizes, int n_in,
                              void* d_out, int out_size)
{
    const float* x = (const float*)d_in[0];
    float4* out = (float4*)d_out;

    // 64 * 48 * 3 = 9216 blocks; each writes 2 i's x 32 j's x 512B = 32KB.
    gcom_kernel<<<64 * IH * JT, 256>>>(x, out);
}

// round 10
// speedup vs baseline: 1.4045x; 1.4045x over previous
#include <cuda_runtime.h>
#include <cuda_bf16.h>

// x (64, 96, 8, 8) fp32 -> out (64, 96, 96, 8, 8, 2) fp32
// out[b,i,j,c1,c2,0] = x[b,i,c1,c2]; out[b,i,j,c1,c2,1] = x[b,j,c1,c2]
//
// Block = (b, i, jt) covering 16 consecutive j's with 128 threads (4 warps).
//   warp w (0..3) handles j = jt*16 + w*4 + {0..3}; lane = k2 (0..31).
// Per thread: 1 xi float2 load (reused) + 4 independent xj loads
//             -> 4 independent 512B-coalesced float4 stores.
// Same per-thread shape as the 46us kernel, but 2x finer CTA granularity
// (shorter store bursts per CTA, less L1tex queue contention, shorter tail).

#define GS  96
#define BLK 64            // 8*8 floats per group block
#define F4  32            // float4 per (b,i,j) pair
#define JT  6             // j-tiles per (b,i): 6 * 16 = 96

__global__ __launch_bounds__(128)
void gcom_kernel(const float* __restrict__ x, float4* __restrict__ out)
{
    unsigned blk = blockIdx.x;             // (b*96 + i)*6 + jt
    unsigned jt  = blk % JT;
    unsigned bi  = blk / JT;               // b*96 + i
    unsigned b   = bi / GS;
    unsigned i   = bi - b * GS;

    unsigned lane = threadIdx.x & 31u;     // k2: float2 index within 64-float block
    unsigned w    = threadIdx.x >> 5;      // warp 0..3
    unsigned j0   = jt * 16 + w * 4;       // first of 4 j's for this warp

    const float2* xrow = (const float2*)(x + (size_t)b * GS * BLK);

    // All loads issued up front (independent; xi reused for 4 stores).
    float2 a  = __ldg(xrow + i * F4 + lane);
    const float2* xj = xrow + j0 * F4 + lane;
    float2 c0 = __ldg(xj);
    float2 c1 = __ldg(xj + F4);
    float2 c2 = __ldg(xj + 2 * F4);
    float2 c3 = __ldg(xj + 3 * F4);

    float4* o = out + ((size_t)bi * GS + j0) * F4 + lane;
    o[0]      = make_float4(a.x, c0.x, a.y, c0.y);
    o[F4]     = make_float4(a.x, c1.x, a.y, c1.y);
    o[2 * F4] = make_float4(a.x, c2.x, a.y, c2.y);
    o[3 * F4] = make_float4(a.x, c3.x, a.y, c3.y);
}

extern "C" void kernel_launch(void* const* d_in, const int* in_sizes, int n_in,
                              void* d_out, int out_size)
{
    const float* x = (const float*)d_in[0];
    float4* out = (float4*)d_out;

    // 64 * 96 * 6 = 36864 blocks; each writes 16 * 512B = 8KB of output.
    gcom_kernel<<<64 * GS * JT, 128>>>(x, out);
}